// round 10
// baseline (speedup 1.0000x reference)
#include <cuda_runtime.h>
#include <cuda_bf16.h>
#include <cstdint>
#include <math.h>

#define B_  4
#define T_  2048
#define C_  1024
#define H_  16
#define Dh_ 64
#define KQV_COLS (3 * C_)   // 3072
#define M_  (B_ * T_)       // 8192

static_assert(Dh_ == 64 && H_ * Dh_ == C_, "head geometry");

// ---------------------------------------------------------------------------
// Device scratch
// ---------------------------------------------------------------------------
__device__ __align__(16) __nv_bfloat16 g_kqvhi[(size_t)M_ * KQV_COLS];
__device__ __align__(16) __nv_bfloat16 g_kqvlo[(size_t)M_ * KQV_COLS];
__device__ __align__(16) __nv_bfloat16 g_xhi [(size_t)M_ * C_];
__device__ __align__(16) __nv_bfloat16 g_xlo [(size_t)M_ * C_];
__device__ __align__(16) __nv_bfloat16 g_wkhi[(size_t)KQV_COLS * C_];
__device__ __align__(16) __nv_bfloat16 g_wklo[(size_t)KQV_COLS * C_];
__device__ __align__(16) __nv_bfloat16 g_wphi[(size_t)C_ * C_];
__device__ __align__(16) __nv_bfloat16 g_wplo[(size_t)C_ * C_];
__device__ __align__(16) __nv_bfloat16 g_ahi [(size_t)M_ * C_];
__device__ __align__(16) __nv_bfloat16 g_alo [(size_t)M_ * C_];

// ---------------------------------------------------------------------------
// PTX helpers
// ---------------------------------------------------------------------------
__device__ __forceinline__ uint32_t smem_u32(const void* p) {
    uint32_t a;
    asm("{ .reg .u64 t; cvta.to.shared.u64 t, %1; cvt.u32.u64 %0, t; }" : "=r"(a) : "l"(p));
    return a;
}
#define LDSM4(r0, r1, r2, r3, addr) \
    asm volatile("ldmatrix.sync.aligned.m8n8.x4.shared.b16 {%0,%1,%2,%3}, [%4];" \
        : "=r"(r0), "=r"(r1), "=r"(r2), "=r"(r3) : "r"(addr))
#define LDSM4T(r0, r1, r2, r3, addr) \
    asm volatile("ldmatrix.sync.aligned.m8n8.x4.trans.shared.b16 {%0,%1,%2,%3}, [%4];" \
        : "=r"(r0), "=r"(r1), "=r"(r2), "=r"(r3) : "r"(addr))
#define MMA16816(d, a, b) \
    asm volatile("mma.sync.aligned.m16n8k16.row.col.f32.bf16.bf16.f32 " \
        "{%0,%1,%2,%3}, {%4,%5,%6,%7}, {%8,%9}, {%0,%1,%2,%3};" \
        : "+f"((d)[0]), "+f"((d)[1]), "+f"((d)[2]), "+f"((d)[3]) \
        : "r"((a)[0]), "r"((a)[1]), "r"((a)[2]), "r"((a)[3]), \
          "r"((b)[0]), "r"((b)[1]))
#define CP_ASYNC16(sdst, gsrc) \
    asm volatile("cp.async.cg.shared.global [%0], [%1], 16;" :: "r"(sdst), "l"(gsrc))
#define CP_COMMIT() asm volatile("cp.async.commit_group;" ::: "memory")
#define CP_WAIT(n)  asm volatile("cp.async.wait_group %0;" :: "n"(n) : "memory")

__device__ __forceinline__ uint32_t pack_bf(__nv_bfloat16 a, __nv_bfloat16 b) {
    return ((uint32_t)__bfloat16_as_ushort(b) << 16) | (uint32_t)__bfloat16_as_ushort(a);
}
__device__ __forceinline__ void split2(float v0, float v1, uint32_t& hi, uint32_t& lo) {
    __nv_bfloat16 h0 = __float2bfloat16(v0), h1 = __float2bfloat16(v1);
    hi = pack_bf(h0, h1);
    lo = pack_bf(__float2bfloat16(v0 - __bfloat162float(h0)),
                 __float2bfloat16(v1 - __bfloat162float(h1)));
}

// ---------------------------------------------------------------------------
// Prep kernels
// ---------------------------------------------------------------------------
__global__ __launch_bounds__(256) void prep_a_kernel(
    const float4* __restrict__ X, uint2* __restrict__ Hi, uint2* __restrict__ Lo)
{
    int idx = blockIdx.x * 256 + threadIdx.x;
    float4 v = X[idx];
    uint32_t h0, l0, h1, l1;
    split2(v.x, v.y, h0, l0);
    split2(v.z, v.w, h1, l1);
    Hi[idx] = make_uint2(h0, h1); Lo[idx] = make_uint2(l0, l1);
}

__global__ void prep_w_kernel(const float* __restrict__ W,
                              __nv_bfloat16* __restrict__ Whi,
                              __nv_bfloat16* __restrict__ Wlo, int K, int N)
{
    __shared__ float t[32][33];
    int nb = blockIdx.x * 32, kb = blockIdx.y * 32;
    int tx = threadIdx.x, ty = threadIdx.y;
    #pragma unroll
    for (int i = 0; i < 4; i++) {
        int k = kb + ty + i * 8;
        t[ty + i * 8][tx] = W[(size_t)k * N + nb + tx];
    }
    __syncthreads();
    #pragma unroll
    for (int i = 0; i < 4; i++) {
        int n = nb + ty + i * 8;
        float v = t[tx][ty + i * 8];
        __nv_bfloat16 h = __float2bfloat16(v);
        Whi[(size_t)n * K + kb + tx] = h;
        Wlo[(size_t)n * K + kb + tx] = __float2bfloat16(v - __bfloat162float(h));
    }
}

// ---------------------------------------------------------------------------
// Split-bf16 GEMM, 4 warps (2x2), warp tile 64x64, 128 threads/CTA.
// ---------------------------------------------------------------------------
#define PADROW 40
#define MAT_BYTES (128 * PADROW * 2)
#define STAGE_B   (4 * MAT_BYTES)
#define GEMM_SMEM (2 * STAGE_B)

__global__ __launch_bounds__(128) void mma_gemm_kernel(
    const __nv_bfloat16* __restrict__ Ahi, const __nv_bfloat16* __restrict__ Alo,
    const __nv_bfloat16* __restrict__ Bhi, const __nv_bfloat16* __restrict__ Blo,
    float* __restrict__ Cc, __nv_bfloat16* __restrict__ Chi,
    __nv_bfloat16* __restrict__ Clo, int M, int N, int K)
{
    extern __shared__ char smem[];
    const uint32_t sb = smem_u32(smem);
    const int tid  = threadIdx.x;
    const int wid  = tid >> 5, lane = tid & 31;
    const int wm   = wid & 1,  wn   = wid >> 1;
    const int m0   = blockIdx.y * 128, n0 = blockIdx.x * 128;
    const int NC   = K / 32;

    const __nv_bfloat16* gsrc[4] = {
        Ahi + (size_t)(m0 + tid) * K,
        Alo + (size_t)(m0 + tid) * K,
        Bhi + (size_t)(n0 + tid) * K,
        Blo + (size_t)(n0 + tid) * K
    };
    const uint32_t sdst_base = tid * (PADROW * 2);

    float acc[4][8][4];
    #pragma unroll
    for (int ma = 0; ma < 4; ma++)
        #pragma unroll
        for (int na = 0; na < 8; na++)
            #pragma unroll
            for (int q = 0; q < 4; q++) acc[ma][na][q] = 0.f;

    auto issue = [&](int c, int s) {
        const int koff = c * 32;
        #pragma unroll
        for (int mtx = 0; mtx < 4; mtx++) {
            uint32_t sd = sb + s * STAGE_B + mtx * MAT_BYTES + sdst_base;
            const __nv_bfloat16* gs = gsrc[mtx] + koff;
            CP_ASYNC16(sd,      gs);
            CP_ASYNC16(sd + 16, gs + 8);
            CP_ASYNC16(sd + 32, gs + 16);
            CP_ASYNC16(sd + 48, gs + 24);
        }
    };

    issue(0, 0); CP_COMMIT();

    for (int c = 0; c < NC; c++) {
        const int s = c & 1;
        CP_WAIT(0);
        __syncthreads();
        if (c + 1 < NC) { issue(c + 1, s ^ 1); CP_COMMIT(); }

        const uint32_t mb = sb + s * STAGE_B;
        #pragma unroll
        for (int h = 0; h < 2; h++) {
            uint32_t bh[8][2], bl[8][2];
            #pragma unroll
            for (int p = 0; p < 4; p++) {
                int row = wn * 64 + p * 16 + (lane & 7) + ((lane >> 4) & 1) * 8;
                uint32_t off = row * (PADROW * 2) + h * 32 + ((lane >> 3) & 1) * 16;
                LDSM4(bh[2*p][0], bh[2*p][1], bh[2*p+1][0], bh[2*p+1][1],
                      mb + 2 * MAT_BYTES + off);
                LDSM4(bl[2*p][0], bl[2*p][1], bl[2*p+1][0], bl[2*p+1][1],
                      mb + 3 * MAT_BYTES + off);
            }
            #pragma unroll
            for (int ma = 0; ma < 4; ma++) {
                uint32_t ah[4], al[4];
                int row = wm * 64 + ma * 16 + (lane & 15);
                uint32_t off = row * (PADROW * 2) + h * 32 + (lane >> 4) * 16;
                LDSM4(ah[0], ah[1], ah[2], ah[3], mb + 0 * MAT_BYTES + off);
                LDSM4(al[0], al[1], al[2], al[3], mb + 1 * MAT_BYTES + off);
                #pragma unroll
                for (int na = 0; na < 8; na++) {
                    MMA16816(acc[ma][na], ah, bh[na]);
                    MMA16816(acc[ma][na], ah, bl[na]);
                    MMA16816(acc[ma][na], al, bh[na]);
                }
            }
        }
    }

    const int g  = lane >> 2;
    const int i2 = (lane & 3) * 2;
    #pragma unroll
    for (int ma = 0; ma < 4; ma++) {
        #pragma unroll
        for (int na = 0; na < 8; na++) {
            int row = m0 + wm * 64 + ma * 16 + g;
            int col = n0 + wn * 64 + na * 8 + i2;
            if (Chi) {
                uint32_t h0, l0, h1, l1;
                split2(acc[ma][na][0], acc[ma][na][1], h0, l0);
                split2(acc[ma][na][2], acc[ma][na][3], h1, l1);
                *(uint32_t*)&Chi[(size_t)row * N + col] = h0;
                *(uint32_t*)&Clo[(size_t)row * N + col] = l0;
                *(uint32_t*)&Chi[(size_t)(row + 8) * N + col] = h1;
                *(uint32_t*)&Clo[(size_t)(row + 8) * N + col] = l1;
            } else {
                *(float2*)&Cc[(size_t)row * N + col] =
                    make_float2(acc[ma][na][0], acc[ma][na][1]);
                *(float2*)&Cc[(size_t)(row + 8) * N + col] =
                    make_float2(acc[ma][na][2], acc[ma][na][3]);
            }
        }
    }
}

// ---------------------------------------------------------------------------
// Flash attention on mma.sync, 4 warps x 32 q-rows (CTA = 128 q), 128 thr.
// FIX vs R9: Q prologue now stages the FULL 128-byte Q rows (8 x 16B per
// matrix per thread), matching the issueKV fix. Q rows are Dh=64 bf16=128B.
// ---------------------------------------------------------------------------
#define FPAD   72
#define FROWB  (FPAD * 2)            // 144
#define FMAT   (64 * FROWB)          // 9216
#define FSTAGE (4 * FMAT)            // 36864
#define FLASH_SMEM (2 * FSTAGE)      // 73728
#define QMATB  (128 * FROWB)         // 18432

__global__ __launch_bounds__(128) void flash_mma_kernel()
{
    extern __shared__ char fsm[];
    const uint32_t sb = smem_u32(fsm);
    const int tid = threadIdx.x, wid = tid >> 5, lane = tid & 31;
    const int bh = blockIdx.y, b = bh >> 4, h = bh & 15;
    const int q0 = blockIdx.x * 128;

    const __nv_bfloat16* khi = g_kqvhi + (size_t)b * T_ * KQV_COLS + h * Dh_;
    const __nv_bfloat16* klo = g_kqvlo + (size_t)b * T_ * KQV_COLS + h * Dh_;

    // ---- Prologue: stage Q rows (FULL 128 B each; hi at 0, lo at QMATB) ----
    {
        size_t go = (size_t)(q0 + tid) * KQV_COLS + C_;   // q at s=1
        uint32_t d0 = sb + tid * FROWB;
        uint32_t d1 = d0 + QMATB;
        #pragma unroll
        for (int i = 0; i < 8; i++) {
            CP_ASYNC16(d0 + i * 16, khi + go + i * 8);
            CP_ASYNC16(d1 + i * 16, klo + go + i * 8);
        }
    }
    CP_COMMIT(); CP_WAIT(0); __syncthreads();

    uint32_t qh[2][4][4], ql[2][4][4];   // [m-atom][k16][frag]
    #pragma unroll
    for (int ma = 0; ma < 2; ma++) {
        int row = wid * 32 + ma * 16 + (lane & 15);
        #pragma unroll
        for (int ks = 0; ks < 4; ks++) {
            uint32_t off = row * FROWB + ks * 32 + (lane >> 4) * 16;
            LDSM4(qh[ma][ks][0], qh[ma][ks][1], qh[ma][ks][2], qh[ma][ks][3], sb + off);
            LDSM4(ql[ma][ks][0], ql[ma][ks][1], ql[ma][ks][2], ql[ma][ks][3], sb + QMATB + off);
        }
    }
    __syncthreads();   // Q staging now reusable as stage buffers

    // KV issue: 64 rows x 128 B x 4 matrices; 2 threads/row, each covers its
    // half*64-byte half of the row => 4 x 16B per matrix per thread.
    auto issueKV = [&](int t, int s) {
        int row = tid >> 1, half = tid & 1;
        size_t go = (size_t)(t * 64 + row) * KQV_COLS + half * 32;   // elements
        uint32_t d = sb + s * FSTAGE + row * FROWB + half * 64;      // bytes
        #pragma unroll
        for (int mtx = 0; mtx < 4; mtx++) {
            const __nv_bfloat16* src =
                (mtx == 0) ? khi + go :
                (mtx == 1) ? klo + go :
                (mtx == 2) ? khi + 2 * C_ + go : klo + 2 * C_ + go;
            uint32_t dd = d + mtx * FMAT;
            CP_ASYNC16(dd,      src);
            CP_ASYNC16(dd + 16, src + 8);
            CP_ASYNC16(dd + 32, src + 16);
            CP_ASYNC16(dd + 48, src + 24);
        }
    };

    float o[2][8][4];
    #pragma unroll
    for (int ma = 0; ma < 2; ma++)
        #pragma unroll
        for (int na = 0; na < 8; na++)
            #pragma unroll
            for (int q = 0; q < 4; q++) o[ma][na][q] = 0.f;
    float mi[2][2] = {{-1e30f, -1e30f}, {-1e30f, -1e30f}};
    float li[2][2] = {{0.f, 0.f}, {0.f, 0.f}};

    issueKV(0, 0); CP_COMMIT();

    const int NT = T_ / 64;
    for (int t = 0; t < NT; t++) {
        const int s = t & 1;
        CP_WAIT(0);
        __syncthreads();
        if (t + 1 < NT) { issueKV(t + 1, s ^ 1); CP_COMMIT(); }

        const uint32_t khm = sb + s * FSTAGE;
        const uint32_t klm = khm + FMAT;
        const uint32_t vhm = khm + 2 * FMAT;
        const uint32_t vlm = khm + 3 * FMAT;

        // ---- S = Q K^T (3-way split) ----
        float sc[2][8][4];
        #pragma unroll
        for (int ma = 0; ma < 2; ma++)
            #pragma unroll
            for (int na = 0; na < 8; na++)
                #pragma unroll
                for (int q = 0; q < 4; q++) sc[ma][na][q] = 0.f;

        #pragma unroll
        for (int ks = 0; ks < 4; ks++) {
            #pragma unroll
            for (int p = 0; p < 4; p++) {
                int brow = p * 16 + (lane & 7) + ((lane >> 4) & 1) * 8;
                uint32_t boff = brow * FROWB + ks * 32 + ((lane >> 3) & 1) * 16;
                uint32_t b0h, b1h, b2h, b3h, b0l, b1l, b2l, b3l;
                LDSM4(b0h, b1h, b2h, b3h, khm + boff);
                LDSM4(b0l, b1l, b2l, b3l, klm + boff);
                uint32_t Bh0[2] = {b0h, b1h}, Bh1[2] = {b2h, b3h};
                uint32_t Bl0[2] = {b0l, b1l}, Bl1[2] = {b2l, b3l};
                #pragma unroll
                for (int ma = 0; ma < 2; ma++) {
                    MMA16816(sc[ma][2*p],   qh[ma][ks], Bh0);
                    MMA16816(sc[ma][2*p],   qh[ma][ks], Bl0);
                    MMA16816(sc[ma][2*p],   ql[ma][ks], Bh0);
                    MMA16816(sc[ma][2*p+1], qh[ma][ks], Bh1);
                    MMA16816(sc[ma][2*p+1], qh[ma][ks], Bl1);
                    MMA16816(sc[ma][2*p+1], ql[ma][ks], Bh1);
                }
            }
        }
        #pragma unroll
        for (int ma = 0; ma < 2; ma++)
            #pragma unroll
            for (int na = 0; na < 8; na++)
                #pragma unroll
                for (int q = 0; q < 4; q++) sc[ma][na][q] *= 0.125f;

        // ---- online softmax ----
        #pragma unroll
        for (int ma = 0; ma < 2; ma++) {
            float scl[2];
            #pragma unroll
            for (int rr = 0; rr < 2; rr++) {
                float rm = -1e30f;
                #pragma unroll
                for (int na = 0; na < 8; na++)
                    rm = fmaxf(rm, fmaxf(sc[ma][na][2*rr], sc[ma][na][2*rr+1]));
                rm = fmaxf(rm, __shfl_xor_sync(0xffffffffu, rm, 1));
                rm = fmaxf(rm, __shfl_xor_sync(0xffffffffu, rm, 2));
                float mnew = fmaxf(mi[ma][rr], rm);
                scl[rr] = __expf(mi[ma][rr] - mnew);
                float rs = 0.f;
                #pragma unroll
                for (int na = 0; na < 8; na++) {
                    sc[ma][na][2*rr]   = __expf(sc[ma][na][2*rr]   - mnew);
                    sc[ma][na][2*rr+1] = __expf(sc[ma][na][2*rr+1] - mnew);
                    rs += sc[ma][na][2*rr] + sc[ma][na][2*rr+1];
                }
                rs += __shfl_xor_sync(0xffffffffu, rs, 1);
                rs += __shfl_xor_sync(0xffffffffu, rs, 2);
                li[ma][rr] = li[ma][rr] * scl[rr] + rs;
                mi[ma][rr] = mnew;
            }
            #pragma unroll
            for (int na = 0; na < 8; na++) {
                o[ma][na][0] *= scl[0]; o[ma][na][1] *= scl[0];
                o[ma][na][2] *= scl[1]; o[ma][na][3] *= scl[1];
            }
        }

        // ---- O += P V (3-way split) ----
        #pragma unroll
        for (int ks = 0; ks < 4; ks++) {
            uint32_t pah[2][4], pal[2][4];
            #pragma unroll
            for (int ma = 0; ma < 2; ma++) {
                split2(sc[ma][2*ks  ][0], sc[ma][2*ks  ][1], pah[ma][0], pal[ma][0]);
                split2(sc[ma][2*ks  ][2], sc[ma][2*ks  ][3], pah[ma][1], pal[ma][1]);
                split2(sc[ma][2*ks+1][0], sc[ma][2*ks+1][1], pah[ma][2], pal[ma][2]);
                split2(sc[ma][2*ks+1][2], sc[ma][2*ks+1][3], pah[ma][3], pal[ma][3]);
            }
            #pragma unroll
            for (int nb = 0; nb < 4; nb++) {
                int vrow = ks * 16 + (lane & 7) + ((lane >> 3) & 1) * 8;
                uint32_t voff = vrow * FROWB + (nb * 16 + (lane >> 4) * 8) * 2;
                uint32_t v0h, v1h, v2h, v3h, v0l, v1l, v2l, v3l;
                LDSM4T(v0h, v1h, v2h, v3h, vhm + voff);
                LDSM4T(v0l, v1l, v2l, v3l, vlm + voff);
                uint32_t Vh0[2] = {v0h, v1h}, Vh1[2] = {v2h, v3h};
                uint32_t Vl0[2] = {v0l, v1l}, Vl1[2] = {v2l, v3l};
                #pragma unroll
                for (int ma = 0; ma < 2; ma++) {
                    MMA16816(o[ma][2*nb],   pah[ma], Vh0);
                    MMA16816(o[ma][2*nb],   pah[ma], Vl0);
                    MMA16816(o[ma][2*nb],   pal[ma], Vh0);
                    MMA16816(o[ma][2*nb+1], pah[ma], Vh1);
                    MMA16816(o[ma][2*nb+1], pah[ma], Vl1);
                    MMA16816(o[ma][2*nb+1], pal[ma], Vh1);
                }
            }
        }
    }

    // ---- Epilogue ----
    const int g  = lane >> 2;
    const int n2 = (lane & 3) * 2;
    #pragma unroll
    for (int ma = 0; ma < 2; ma++) {
        const float inv0 = 1.0f / li[ma][0], inv1 = 1.0f / li[ma][1];
        const size_t row0 = (size_t)b * T_ + q0 + wid * 32 + ma * 16 + g;
        #pragma unroll
        for (int na = 0; na < 8; na++) {
            int col = h * Dh_ + na * 8 + n2;
            uint32_t h0, l0, h1, l1;
            split2(o[ma][na][0] * inv0, o[ma][na][1] * inv0, h0, l0);
            split2(o[ma][na][2] * inv1, o[ma][na][3] * inv1, h1, l1);
            *(uint32_t*)&g_ahi[row0 * C_ + col] = h0;
            *(uint32_t*)&g_alo[row0 * C_ + col] = l0;
            *(uint32_t*)&g_ahi[(row0 + 8) * C_ + col] = h1;
            *(uint32_t*)&g_alo[(row0 + 8) * C_ + col] = l1;
        }
    }
}

// ---------------------------------------------------------------------------
extern "C" void kernel_launch(void* const* d_in, const int* in_sizes, int n_in,
                              void* d_out, int out_size)
{
    const float* x     = (const float*)d_in[0];
    const float* Wkqv  = (const float*)d_in[1];
    const float* Wproj = (const float*)d_in[2];
    float* out = (float*)d_out;

    static __nv_bfloat16* p_kqvhi = nullptr;
    static __nv_bfloat16 *p_kqvlo, *p_xhi, *p_xlo, *p_wkhi, *p_wklo,
                         *p_wphi, *p_wplo, *p_ahi, *p_alo;
    if (!p_kqvhi) {
        cudaGetSymbolAddress((void**)&p_kqvhi, g_kqvhi);
        cudaGetSymbolAddress((void**)&p_kqvlo, g_kqvlo);
        cudaGetSymbolAddress((void**)&p_xhi,  g_xhi);
        cudaGetSymbolAddress((void**)&p_xlo,  g_xlo);
        cudaGetSymbolAddress((void**)&p_wkhi, g_wkhi);
        cudaGetSymbolAddress((void**)&p_wklo, g_wklo);
        cudaGetSymbolAddress((void**)&p_wphi, g_wphi);
        cudaGetSymbolAddress((void**)&p_wplo, g_wplo);
        cudaGetSymbolAddress((void**)&p_ahi,  g_ahi);
        cudaGetSymbolAddress((void**)&p_alo,  g_alo);
        cudaFuncSetAttribute(mma_gemm_kernel,
                             cudaFuncAttributeMaxDynamicSharedMemorySize, GEMM_SMEM);
        cudaFuncSetAttribute(flash_mma_kernel,
                             cudaFuncAttributeMaxDynamicSharedMemorySize, FLASH_SMEM);
    }

    prep_a_kernel<<<(M_ * C_) / 4 / 256, 256>>>((const float4*)x, (uint2*)p_xhi, (uint2*)p_xlo);
    prep_w_kernel<<<dim3(KQV_COLS / 32, C_ / 32), dim3(32, 8)>>>(Wkqv, p_wkhi, p_wklo, C_, KQV_COLS);
    prep_w_kernel<<<dim3(C_ / 32, C_ / 32), dim3(32, 8)>>>(Wproj, p_wphi, p_wplo, C_, C_);

    mma_gemm_kernel<<<dim3(KQV_COLS / 128, M_ / 128), 128, GEMM_SMEM>>>(
        p_xhi, p_xlo, p_wkhi, p_wklo, nullptr, p_kqvhi, p_kqvlo, M_, KQV_COLS, C_);

    flash_mma_kernel<<<dim3(T_ / 128, B_ * H_), 128, FLASH_SMEM>>>();

    mma_gemm_kernel<<<dim3(C_ / 128, M_ / 128), 128, GEMM_SMEM>>>(
        p_ahi, p_alo, p_wphi, p_wplo, out, nullptr, nullptr, M_, C_, C_);
}

// round 11
// speedup vs baseline: 1.7625x; 1.7625x over previous
#include <cuda_runtime.h>
#include <cuda_bf16.h>
#include <cstdint>
#include <math.h>

#define B_  4
#define T_  2048
#define C_  1024
#define H_  16
#define Dh_ 64
#define KQV_COLS (3 * C_)   // 3072
#define M_  (B_ * T_)       // 8192

static_assert(Dh_ == 64 && H_ * Dh_ == C_, "head geometry");

// ---------------------------------------------------------------------------
// Device scratch
// ---------------------------------------------------------------------------
__device__ __align__(16) __nv_bfloat16 g_kqvhi[(size_t)M_ * KQV_COLS];
__device__ __align__(16) __nv_bfloat16 g_kqvlo[(size_t)M_ * KQV_COLS];
__device__ __align__(16) __nv_bfloat16 g_xhi [(size_t)M_ * C_];
__device__ __align__(16) __nv_bfloat16 g_xlo [(size_t)M_ * C_];
__device__ __align__(16) __nv_bfloat16 g_wkhi[(size_t)KQV_COLS * C_];
__device__ __align__(16) __nv_bfloat16 g_wklo[(size_t)KQV_COLS * C_];
__device__ __align__(16) __nv_bfloat16 g_wphi[(size_t)C_ * C_];
__device__ __align__(16) __nv_bfloat16 g_wplo[(size_t)C_ * C_];
__device__ __align__(16) __nv_bfloat16 g_ahi [(size_t)M_ * C_];
__device__ __align__(16) __nv_bfloat16 g_alo [(size_t)M_ * C_];

// ---------------------------------------------------------------------------
// PTX helpers
// ---------------------------------------------------------------------------
__device__ __forceinline__ uint32_t smem_u32(const void* p) {
    uint32_t a;
    asm("{ .reg .u64 t; cvta.to.shared.u64 t, %1; cvt.u32.u64 %0, t; }" : "=r"(a) : "l"(p));
    return a;
}
#define LDSM4(r0, r1, r2, r3, addr) \
    asm volatile("ldmatrix.sync.aligned.m8n8.x4.shared.b16 {%0,%1,%2,%3}, [%4];" \
        : "=r"(r0), "=r"(r1), "=r"(r2), "=r"(r3) : "r"(addr))
#define LDSM4T(r0, r1, r2, r3, addr) \
    asm volatile("ldmatrix.sync.aligned.m8n8.x4.trans.shared.b16 {%0,%1,%2,%3}, [%4];" \
        : "=r"(r0), "=r"(r1), "=r"(r2), "=r"(r3) : "r"(addr))
#define MMA16816(d, a, b) \
    asm volatile("mma.sync.aligned.m16n8k16.row.col.f32.bf16.bf16.f32 " \
        "{%0,%1,%2,%3}, {%4,%5,%6,%7}, {%8,%9}, {%0,%1,%2,%3};" \
        : "+f"((d)[0]), "+f"((d)[1]), "+f"((d)[2]), "+f"((d)[3]) \
        : "r"((a)[0]), "r"((a)[1]), "r"((a)[2]), "r"((a)[3]), \
          "r"((b)[0]), "r"((b)[1]))
#define CP_ASYNC16(sdst, gsrc) \
    asm volatile("cp.async.cg.shared.global [%0], [%1], 16;" :: "r"(sdst), "l"(gsrc))
#define CP_COMMIT() asm volatile("cp.async.commit_group;" ::: "memory")
#define CP_WAIT(n)  asm volatile("cp.async.wait_group %0;" :: "n"(n) : "memory")

__device__ __forceinline__ uint32_t pack_bf(__nv_bfloat16 a, __nv_bfloat16 b) {
    return ((uint32_t)__bfloat16_as_ushort(b) << 16) | (uint32_t)__bfloat16_as_ushort(a);
}
__device__ __forceinline__ void split2(float v0, float v1, uint32_t& hi, uint32_t& lo) {
    __nv_bfloat16 h0 = __float2bfloat16(v0), h1 = __float2bfloat16(v1);
    hi = pack_bf(h0, h1);
    lo = pack_bf(__float2bfloat16(v0 - __bfloat162float(h0)),
                 __float2bfloat16(v1 - __bfloat162float(h1)));
}

// ---------------------------------------------------------------------------
// Prep kernels (unchanged)
// ---------------------------------------------------------------------------
__global__ __launch_bounds__(256) void prep_a_kernel(
    const float4* __restrict__ X, uint2* __restrict__ Hi, uint2* __restrict__ Lo)
{
    int idx = blockIdx.x * 256 + threadIdx.x;
    float4 v = X[idx];
    uint32_t h0, l0, h1, l1;
    split2(v.x, v.y, h0, l0);
    split2(v.z, v.w, h1, l1);
    Hi[idx] = make_uint2(h0, h1); Lo[idx] = make_uint2(l0, l1);
}

__global__ void prep_w_kernel(const float* __restrict__ W,
                              __nv_bfloat16* __restrict__ Whi,
                              __nv_bfloat16* __restrict__ Wlo, int K, int N)
{
    __shared__ float t[32][33];
    int nb = blockIdx.x * 32, kb = blockIdx.y * 32;
    int tx = threadIdx.x, ty = threadIdx.y;
    #pragma unroll
    for (int i = 0; i < 4; i++) {
        int k = kb + ty + i * 8;
        t[ty + i * 8][tx] = W[(size_t)k * N + nb + tx];
    }
    __syncthreads();
    #pragma unroll
    for (int i = 0; i < 4; i++) {
        int n = nb + ty + i * 8;
        float v = t[tx][ty + i * 8];
        __nv_bfloat16 h = __float2bfloat16(v);
        Whi[(size_t)n * K + kb + tx] = h;
        Wlo[(size_t)n * K + kb + tx] = __float2bfloat16(v - __bfloat162float(h));
    }
}

// ---------------------------------------------------------------------------
// Split-bf16 GEMM on mma.sync — EXACT R7 configuration (8 warps 4x2, 256 thr,
// warp tile 32x64, double-buffered, regs ~126, 2 CTAs/SM).
// ---------------------------------------------------------------------------
#define PADROW 40
#define MAT_BYTES (128 * PADROW * 2)
#define STAGE_B   (4 * MAT_BYTES)
#define GEMM_SMEM (2 * STAGE_B)

__global__ __launch_bounds__(256) void mma_gemm_kernel(
    const __nv_bfloat16* __restrict__ Ahi, const __nv_bfloat16* __restrict__ Alo,
    const __nv_bfloat16* __restrict__ Bhi, const __nv_bfloat16* __restrict__ Blo,
    float* __restrict__ Cc, __nv_bfloat16* __restrict__ Chi,
    __nv_bfloat16* __restrict__ Clo, int M, int N, int K)
{
    extern __shared__ char smem[];
    const uint32_t sb = smem_u32(smem);
    const int tid  = threadIdx.x;
    const int wid  = tid >> 5, lane = tid & 31;
    const int wm   = wid & 3,  wn   = wid >> 2;
    const int m0   = blockIdx.y * 128, n0 = blockIdx.x * 128;
    const int NC   = K / 32;

    const int r    = tid >> 1;
    const int half = tid & 1;
    const __nv_bfloat16* gsrc[4] = {
        Ahi + (size_t)(m0 + r) * K + half * 16,
        Alo + (size_t)(m0 + r) * K + half * 16,
        Bhi + (size_t)(n0 + r) * K + half * 16,
        Blo + (size_t)(n0 + r) * K + half * 16
    };
    const uint32_t sdst_base = r * (PADROW * 2) + half * 32;

    float acc[2][8][4];
    #pragma unroll
    for (int ma = 0; ma < 2; ma++)
        #pragma unroll
        for (int na = 0; na < 8; na++)
            #pragma unroll
            for (int q = 0; q < 4; q++) acc[ma][na][q] = 0.f;

    auto issue = [&](int c, int s) {
        const int koff = c * 32;
        #pragma unroll
        for (int mtx = 0; mtx < 4; mtx++) {
            uint32_t sd = sb + s * STAGE_B + mtx * MAT_BYTES + sdst_base;
            const __nv_bfloat16* gs = gsrc[mtx] + koff;
            CP_ASYNC16(sd,      gs);
            CP_ASYNC16(sd + 16, gs + 8);
        }
    };

    issue(0, 0); CP_COMMIT();

    for (int c = 0; c < NC; c++) {
        const int s = c & 1;
        if (c + 1 < NC) { issue(c + 1, s ^ 1); CP_COMMIT(); CP_WAIT(1); }
        else            { CP_WAIT(0); }
        __syncthreads();

        const uint32_t mb = sb + s * STAGE_B;
        #pragma unroll
        for (int h = 0; h < 2; h++) {
            uint32_t ah[2][4], al[2][4];
            #pragma unroll
            for (int ma = 0; ma < 2; ma++) {
                int row = wm * 32 + ma * 16 + (lane & 15);
                uint32_t off = row * (PADROW * 2) + h * 32 + (lane >> 4) * 16;
                LDSM4(ah[ma][0], ah[ma][1], ah[ma][2], ah[ma][3], mb + 0 * MAT_BYTES + off);
                LDSM4(al[ma][0], al[ma][1], al[ma][2], al[ma][3], mb + 1 * MAT_BYTES + off);
            }
            uint32_t bh[8][2], bl[8][2];
            #pragma unroll
            for (int p = 0; p < 4; p++) {
                int row = wn * 64 + p * 16 + (lane & 7) + ((lane >> 4) & 1) * 8;
                uint32_t off = row * (PADROW * 2) + h * 32 + ((lane >> 3) & 1) * 16;
                LDSM4(bh[2*p][0], bh[2*p][1], bh[2*p+1][0], bh[2*p+1][1],
                      mb + 2 * MAT_BYTES + off);
                LDSM4(bl[2*p][0], bl[2*p][1], bl[2*p+1][0], bl[2*p+1][1],
                      mb + 3 * MAT_BYTES + off);
            }
            #pragma unroll
            for (int ma = 0; ma < 2; ma++)
                #pragma unroll
                for (int na = 0; na < 8; na++) {
                    MMA16816(acc[ma][na], ah[ma], bh[na]);
                    MMA16816(acc[ma][na], ah[ma], bl[na]);
                    MMA16816(acc[ma][na], al[ma], bh[na]);
                }
        }
        __syncthreads();
    }

    const int g  = lane >> 2;
    const int i2 = (lane & 3) * 2;
    #pragma unroll
    for (int ma = 0; ma < 2; ma++) {
        #pragma unroll
        for (int na = 0; na < 8; na++) {
            int row = m0 + wm * 32 + ma * 16 + g;
            int col = n0 + wn * 64 + na * 8 + i2;
            if (Chi) {
                uint32_t h0, l0, h1, l1;
                split2(acc[ma][na][0], acc[ma][na][1], h0, l0);
                split2(acc[ma][na][2], acc[ma][na][3], h1, l1);
                *(uint32_t*)&Chi[(size_t)row * N + col] = h0;
                *(uint32_t*)&Clo[(size_t)row * N + col] = l0;
                *(uint32_t*)&Chi[(size_t)(row + 8) * N + col] = h1;
                *(uint32_t*)&Clo[(size_t)(row + 8) * N + col] = l1;
            } else {
                *(float2*)&Cc[(size_t)row * N + col] =
                    make_float2(acc[ma][na][0], acc[ma][na][1]);
                *(float2*)&Cc[(size_t)(row + 8) * N + col] =
                    make_float2(acc[ma][na][2], acc[ma][na][3]);
            }
        }
    }
}

// ---------------------------------------------------------------------------
// Flash attention on mma.sync. 256 threads, 8 warps x 32 q-rows => CTA = 256 q.
// K/V LDSM traffic per iteration unchanged vs R7, but serves 2x queries.
// 3-stage cp.async pipeline, single __syncthreads per iteration.
// ---------------------------------------------------------------------------
#define FPAD   72
#define FROWB  (FPAD * 2)            // 144
#define FMAT   (64 * FROWB)          // 9216
#define FSTAGE (4 * FMAT)            // 36864
#define FLASH_SMEM (3 * FSTAGE)      // 110592
#define QMATB  (256 * FROWB)         // 36864 (Q hi staging; lo right after)

static_assert(2 * QMATB <= FLASH_SMEM, "Q staging fits in stage area");

__global__ __launch_bounds__(256) void flash_mma_kernel()
{
    extern __shared__ char fsm[];
    const uint32_t sb = smem_u32(fsm);
    const int tid = threadIdx.x, wid = tid >> 5, lane = tid & 31;
    const int bh = blockIdx.y, b = bh >> 4, h = bh & 15;
    const int q0 = blockIdx.x * 256;

    const __nv_bfloat16* khi = g_kqvhi + (size_t)b * T_ * KQV_COLS + h * Dh_;
    const __nv_bfloat16* klo = g_kqvlo + (size_t)b * T_ * KQV_COLS + h * Dh_;

    // ---- Prologue: stage Q rows (FULL 128 B each; hi at 0, lo at QMATB).
    //      256 threads x 1 row each.
    {
        size_t go = (size_t)(q0 + tid) * KQV_COLS + C_;   // q at s=1
        uint32_t d0 = sb + tid * FROWB;
        uint32_t d1 = d0 + QMATB;
        #pragma unroll
        for (int i = 0; i < 8; i++) {
            CP_ASYNC16(d0 + i * 16, khi + go + i * 8);
            CP_ASYNC16(d1 + i * 16, klo + go + i * 8);
        }
    }
    CP_COMMIT(); CP_WAIT(0); __syncthreads();

    uint32_t qh[2][4][4], ql[2][4][4];   // [m-atom][k16][frag]
    #pragma unroll
    for (int ma = 0; ma < 2; ma++) {
        int row = wid * 32 + ma * 16 + (lane & 15);
        #pragma unroll
        for (int ks = 0; ks < 4; ks++) {
            uint32_t off = row * FROWB + ks * 32 + (lane >> 4) * 16;
            LDSM4(qh[ma][ks][0], qh[ma][ks][1], qh[ma][ks][2], qh[ma][ks][3], sb + off);
            LDSM4(ql[ma][ks][0], ql[ma][ks][1], ql[ma][ks][2], ql[ma][ks][3], sb + QMATB + off);
        }
    }
    __syncthreads();   // Q staging area now reusable as stage buffers

    // KV issue (R7-verified geometry): 64 rows x 128 B x 4 matrices,
    // 4 threads/row, each thread covers its 32-byte quarter per matrix.
    auto issueKV = [&](int t, int s) {
        int row = tid >> 2, c4 = tid & 3;
        size_t go = (size_t)(t * 64 + row) * KQV_COLS + c4 * 16;   // elements
        uint32_t d = sb + s * FSTAGE + row * FROWB + c4 * 32;      // bytes
        CP_ASYNC16(d + 0 * FMAT,      khi + go);
        CP_ASYNC16(d + 0 * FMAT + 16, khi + go + 8);
        CP_ASYNC16(d + 1 * FMAT,      klo + go);
        CP_ASYNC16(d + 1 * FMAT + 16, klo + go + 8);
        CP_ASYNC16(d + 2 * FMAT,      khi + 2 * C_ + go);
        CP_ASYNC16(d + 2 * FMAT + 16, khi + 2 * C_ + go + 8);
        CP_ASYNC16(d + 3 * FMAT,      klo + 2 * C_ + go);
        CP_ASYNC16(d + 3 * FMAT + 16, klo + 2 * C_ + go + 8);
    };

    float o[2][8][4];
    #pragma unroll
    for (int ma = 0; ma < 2; ma++)
        #pragma unroll
        for (int na = 0; na < 8; na++)
            #pragma unroll
            for (int q = 0; q < 4; q++) o[ma][na][q] = 0.f;
    float mi[2][2] = {{-1e30f, -1e30f}, {-1e30f, -1e30f}};
    float li[2][2] = {{0.f, 0.f}, {0.f, 0.f}};

    issueKV(0, 0); CP_COMMIT();
    issueKV(1, 1); CP_COMMIT();

    const int NT = T_ / 64;   // 32
    for (int t = 0; t < NT; t++) {
        const int s = t % 3;
        if (t + 1 < NT) CP_WAIT(1); else CP_WAIT(0);
        __syncthreads();
        if (t + 2 < NT) { issueKV(t + 2, (t + 2) % 3); CP_COMMIT(); }

        const uint32_t khm = sb + s * FSTAGE;
        const uint32_t klm = khm + FMAT;
        const uint32_t vhm = khm + 2 * FMAT;
        const uint32_t vlm = khm + 3 * FMAT;

        // ---- S = Q K^T (3-way split) ----
        float sc[2][8][4];
        #pragma unroll
        for (int ma = 0; ma < 2; ma++)
            #pragma unroll
            for (int na = 0; na < 8; na++)
                #pragma unroll
                for (int q = 0; q < 4; q++) sc[ma][na][q] = 0.f;

        #pragma unroll
        for (int ks = 0; ks < 4; ks++) {
            #pragma unroll
            for (int p = 0; p < 4; p++) {
                int brow = p * 16 + (lane & 7) + ((lane >> 4) & 1) * 8;
                uint32_t boff = brow * FROWB + ks * 32 + ((lane >> 3) & 1) * 16;
                uint32_t b0h, b1h, b2h, b3h, b0l, b1l, b2l, b3l;
                LDSM4(b0h, b1h, b2h, b3h, khm + boff);
                LDSM4(b0l, b1l, b2l, b3l, klm + boff);
                uint32_t Bh0[2] = {b0h, b1h}, Bh1[2] = {b2h, b3h};
                uint32_t Bl0[2] = {b0l, b1l}, Bl1[2] = {b2l, b3l};
                #pragma unroll
                for (int ma = 0; ma < 2; ma++) {
                    MMA16816(sc[ma][2*p],   qh[ma][ks], Bh0);
                    MMA16816(sc[ma][2*p],   qh[ma][ks], Bl0);
                    MMA16816(sc[ma][2*p],   ql[ma][ks], Bh0);
                    MMA16816(sc[ma][2*p+1], qh[ma][ks], Bh1);
                    MMA16816(sc[ma][2*p+1], qh[ma][ks], Bl1);
                    MMA16816(sc[ma][2*p+1], ql[ma][ks], Bh1);
                }
            }
        }
        #pragma unroll
        for (int ma = 0; ma < 2; ma++)
            #pragma unroll
            for (int na = 0; na < 8; na++)
                #pragma unroll
                for (int q = 0; q < 4; q++) sc[ma][na][q] *= 0.125f;

        // ---- online softmax ----
        #pragma unroll
        for (int ma = 0; ma < 2; ma++) {
            float scl[2];
            #pragma unroll
            for (int rr = 0; rr < 2; rr++) {
                float rm = -1e30f;
                #pragma unroll
                for (int na = 0; na < 8; na++)
                    rm = fmaxf(rm, fmaxf(sc[ma][na][2*rr], sc[ma][na][2*rr+1]));
                rm = fmaxf(rm, __shfl_xor_sync(0xffffffffu, rm, 1));
                rm = fmaxf(rm, __shfl_xor_sync(0xffffffffu, rm, 2));
                float mnew = fmaxf(mi[ma][rr], rm);
                scl[rr] = __expf(mi[ma][rr] - mnew);
                float rs = 0.f;
                #pragma unroll
                for (int na = 0; na < 8; na++) {
                    sc[ma][na][2*rr]   = __expf(sc[ma][na][2*rr]   - mnew);
                    sc[ma][na][2*rr+1] = __expf(sc[ma][na][2*rr+1] - mnew);
                    rs += sc[ma][na][2*rr] + sc[ma][na][2*rr+1];
                }
                rs += __shfl_xor_sync(0xffffffffu, rs, 1);
                rs += __shfl_xor_sync(0xffffffffu, rs, 2);
                li[ma][rr] = li[ma][rr] * scl[rr] + rs;
                mi[ma][rr] = mnew;
            }
            #pragma unroll
            for (int na = 0; na < 8; na++) {
                o[ma][na][0] *= scl[0]; o[ma][na][1] *= scl[0];
                o[ma][na][2] *= scl[1]; o[ma][na][3] *= scl[1];
            }
        }

        // ---- O += P V (3-way split) ----
        #pragma unroll
        for (int ks = 0; ks < 4; ks++) {
            uint32_t pah[2][4], pal[2][4];
            #pragma unroll
            for (int ma = 0; ma < 2; ma++) {
                split2(sc[ma][2*ks  ][0], sc[ma][2*ks  ][1], pah[ma][0], pal[ma][0]);
                split2(sc[ma][2*ks  ][2], sc[ma][2*ks  ][3], pah[ma][1], pal[ma][1]);
                split2(sc[ma][2*ks+1][0], sc[ma][2*ks+1][1], pah[ma][2], pal[ma][2]);
                split2(sc[ma][2*ks+1][2], sc[ma][2*ks+1][3], pah[ma][3], pal[ma][3]);
            }
            #pragma unroll
            for (int nb = 0; nb < 4; nb++) {
                int vrow = ks * 16 + (lane & 7) + ((lane >> 3) & 1) * 8;
                uint32_t voff = vrow * FROWB + (nb * 16 + (lane >> 4) * 8) * 2;
                uint32_t v0h, v1h, v2h, v3h, v0l, v1l, v2l, v3l;
                LDSM4T(v0h, v1h, v2h, v3h, vhm + voff);
                LDSM4T(v0l, v1l, v2l, v3l, vlm + voff);
                uint32_t Vh0[2] = {v0h, v1h}, Vh1[2] = {v2h, v3h};
                uint32_t Vl0[2] = {v0l, v1l}, Vl1[2] = {v2l, v3l};
                #pragma unroll
                for (int ma = 0; ma < 2; ma++) {
                    MMA16816(o[ma][2*nb],   pah[ma], Vh0);
                    MMA16816(o[ma][2*nb],   pah[ma], Vl0);
                    MMA16816(o[ma][2*nb],   pal[ma], Vh0);
                    MMA16816(o[ma][2*nb+1], pah[ma], Vh1);
                    MMA16816(o[ma][2*nb+1], pah[ma], Vl1);
                    MMA16816(o[ma][2*nb+1], pal[ma], Vh1);
                }
            }
        }
    }

    // ---- Epilogue ----
    const int g  = lane >> 2;
    const int n2 = (lane & 3) * 2;
    #pragma unroll
    for (int ma = 0; ma < 2; ma++) {
        const float inv0 = 1.0f / li[ma][0], inv1 = 1.0f / li[ma][1];
        const size_t row0 = (size_t)b * T_ + q0 + wid * 32 + ma * 16 + g;
        #pragma unroll
        for (int na = 0; na < 8; na++) {
            int col = h * Dh_ + na * 8 + n2;
            uint32_t h0, l0, h1, l1;
            split2(o[ma][na][0] * inv0, o[ma][na][1] * inv0, h0, l0);
            split2(o[ma][na][2] * inv1, o[ma][na][3] * inv1, h1, l1);
            *(uint32_t*)&g_ahi[row0 * C_ + col] = h0;
            *(uint32_t*)&g_alo[row0 * C_ + col] = l0;
            *(uint32_t*)&g_ahi[(row0 + 8) * C_ + col] = h1;
            *(uint32_t*)&g_alo[(row0 + 8) * C_ + col] = l1;
        }
    }
}

// ---------------------------------------------------------------------------
extern "C" void kernel_launch(void* const* d_in, const int* in_sizes, int n_in,
                              void* d_out, int out_size)
{
    const float* x     = (const float*)d_in[0];
    const float* Wkqv  = (const float*)d_in[1];
    const float* Wproj = (const float*)d_in[2];
    float* out = (float*)d_out;

    static __nv_bfloat16* p_kqvhi = nullptr;
    static __nv_bfloat16 *p_kqvlo, *p_xhi, *p_xlo, *p_wkhi, *p_wklo,
                         *p_wphi, *p_wplo, *p_ahi, *p_alo;
    if (!p_kqvhi) {
        cudaGetSymbolAddress((void**)&p_kqvhi, g_kqvhi);
        cudaGetSymbolAddress((void**)&p_kqvlo, g_kqvlo);
        cudaGetSymbolAddress((void**)&p_xhi,  g_xhi);
        cudaGetSymbolAddress((void**)&p_xlo,  g_xlo);
        cudaGetSymbolAddress((void**)&p_wkhi, g_wkhi);
        cudaGetSymbolAddress((void**)&p_wklo, g_wklo);
        cudaGetSymbolAddress((void**)&p_wphi, g_wphi);
        cudaGetSymbolAddress((void**)&p_wplo, g_wplo);
        cudaGetSymbolAddress((void**)&p_ahi,  g_ahi);
        cudaGetSymbolAddress((void**)&p_alo,  g_alo);
        cudaFuncSetAttribute(mma_gemm_kernel,
                             cudaFuncAttributeMaxDynamicSharedMemorySize, GEMM_SMEM);
        cudaFuncSetAttribute(flash_mma_kernel,
                             cudaFuncAttributeMaxDynamicSharedMemorySize, FLASH_SMEM);
    }

    prep_a_kernel<<<(M_ * C_) / 4 / 256, 256>>>((const float4*)x, (uint2*)p_xhi, (uint2*)p_xlo);
    prep_w_kernel<<<dim3(KQV_COLS / 32, C_ / 32), dim3(32, 8)>>>(Wkqv, p_wkhi, p_wklo, C_, KQV_COLS);
    prep_w_kernel<<<dim3(C_ / 32, C_ / 32), dim3(32, 8)>>>(Wproj, p_wphi, p_wplo, C_, C_);

    mma_gemm_kernel<<<dim3(KQV_COLS / 128, M_ / 128), 256, GEMM_SMEM>>>(
        p_xhi, p_xlo, p_wkhi, p_wklo, nullptr, p_kqvhi, p_kqvlo, M_, KQV_COLS, C_);

    flash_mma_kernel<<<dim3(T_ / 256, B_ * H_), 256, FLASH_SMEM>>>();

    mma_gemm_kernel<<<dim3(C_ / 128, M_ / 128), 256, GEMM_SMEM>>>(
        p_ahi, p_alo, p_wphi, p_wplo, out, nullptr, nullptr, M_, C_, C_);
}